// round 13
// baseline (speedup 1.0000x reference)
#include <cuda_runtime.h>
#include <cuda_fp16.h>
#include <cstdint>
#include <cstddef>

// ---------------------------------------------------------------------------
// Problem constants
// ---------------------------------------------------------------------------
#define MDIM 4096
#define KDIM 4096
#define NDIM 12288
// GROUP = 64

// GEMM tiling: persistent CTAs. CTA tile 128x128, TK=64, 4 warps (2m x 2n,
// warp tile 64x64), 3 stages x 32KB ring continuing ACROSS tiles, bulk-async
// fills, ratio 4 MMA:LDSM, 2 CTAs/SM.
#define TM 128
#define TN 128
#define TKC 64
#define STAGES 3
#define KITERS (KDIM / TKC)           // 64
#define TILES_M (MDIM / TM)           // 32
#define TILES_N (NDIM / TN)           // 96
#define NTILES (TILES_M * TILES_N)    // 3072
#define GRIDSZ 296                    // 2 CTAs/SM x 148 SMs
#define STAGE_BYTES 32768             // A 16K + B 16K
#define NTHREADS 128
#define SMEM_TOTAL (1024 + STAGES * STAGE_BYTES)   // 99328 -> 2 CTAs/SM

// ---------------------------------------------------------------------------
// Scratch (device globals: no allocation allowed)
// g_Xh: X in fp16, 64-k-chunk tiled + swizzled: [kc][m][8 chunks of 16B],
//       chunk c of row m stored at position (c ^ (m&7)).
// g_Wt: W^T in fp16, same tiled+swizzled layout over n: [kc][n][8 chunks].
// ---------------------------------------------------------------------------
__device__ __half g_Xh[(size_t)MDIM * KDIM];   // 32 MB
__device__ __half g_Wt[(size_t)NDIM * KDIM];   // 96 MB

// ---------------------------------------------------------------------------
// Profiling pad: rotates the fixed ncu capture slot.
// ---------------------------------------------------------------------------
__global__ void prof_pad_kernel() {}

// ---------------------------------------------------------------------------
// Prepass 1: fp16 X -> tiled+swizzled layout. One 16B chunk per thread.
// ---------------------------------------------------------------------------
__global__ void __launch_bounds__(256) tile_x_kernel(const float4* __restrict__ x) {
    const size_t i = (size_t)blockIdx.x * 256 + threadIdx.x;  // chunk id, M*K/8 total
    const int m  = (int)(i >> 9);      // K/8 = 512 chunks per row
    const int c8 = (int)(i & 511);
    const int kc = c8 >> 3;
    const int c  = c8 & 7;
    float4 v0 = x[(size_t)m * 1024 + c8 * 2];
    float4 v1 = x[(size_t)m * 1024 + c8 * 2 + 1];
    __half2 h0 = __floats2half2_rn(v0.x, v0.y);
    __half2 h1 = __floats2half2_rn(v0.z, v0.w);
    __half2 h2 = __floats2half2_rn(v1.x, v1.y);
    __half2 h3 = __floats2half2_rn(v1.z, v1.w);
    uint4 p;
    p.x = reinterpret_cast<uint32_t&>(h0);
    p.y = reinterpret_cast<uint32_t&>(h1);
    p.z = reinterpret_cast<uint32_t&>(h2);
    p.w = reinterpret_cast<uint32_t&>(h3);
    const size_t idx16 = ((size_t)kc * MDIM + m) * 8 + (c ^ (m & 7));
    reinterpret_cast<uint4*>(g_Xh)[idx16] = p;
}

// ---------------------------------------------------------------------------
// Prepass 2: dequant q[K,N] (codes 0..3) -> fp16 W^T tiled+swizzled.
// w[k,n] = q[k,n]*scale[k/64,n] + zp[k/64,n]
// ---------------------------------------------------------------------------
__global__ void __launch_bounds__(256) dequant_kernel(const int* __restrict__ q,
                                                      const float* __restrict__ scale,
                                                      const float* __restrict__ zp) {
    __shared__ __half tile[32][34];
    const int n0 = blockIdx.x * 32;
    const int k0 = blockIdx.y * 32;   // 32 | 64 -> single group per k-tile
    const int tx = threadIdx.x;       // 0..31
    const int ty = threadIdx.y;       // 0..7
    const int g = k0 >> 6;
    const float s = scale[(size_t)g * NDIM + n0 + tx];
    const float z = zp[(size_t)g * NDIM + n0 + tx];
#pragma unroll
    for (int r = 0; r < 4; ++r) {
        int k = k0 + ty + r * 8;
        int qq = q[(size_t)k * NDIM + n0 + tx];
        tile[ty + r * 8][tx] = __float2half((float)qq * s + z);
    }
    __syncthreads();
#pragma unroll
    for (int r = 0; r < 4; ++r) {
        int n = n0 + ty + r * 8;
        int k = k0 + tx;
        int kc = k >> 6;
        int c  = (k >> 3) & 7;
        size_t byte = (((size_t)kc * NDIM + n) * 8 + (c ^ (n & 7))) * 16 + (size_t)(k & 7) * 2;
        *reinterpret_cast<__half*>(reinterpret_cast<char*>(g_Wt) + byte) = tile[tx][ty + r * 8];
    }
}

// ---------------------------------------------------------------------------
// PTX helpers (sm_90-standard, compute_103-safe)
// ---------------------------------------------------------------------------
__device__ __forceinline__ uint32_t smem_u32(const void* p) {
    uint32_t a;
    asm("{ .reg .u64 t; cvta.to.shared.u64 t, %1; cvt.u32.u64 %0, t; }" : "=r"(a) : "l"(p));
    return a;
}

__device__ __forceinline__ void mbar_init(uint32_t a, uint32_t cnt) {
    asm volatile("mbarrier.init.shared.b64 [%0], %1;" :: "r"(a), "r"(cnt) : "memory");
}

__device__ __forceinline__ void mbar_expect(uint32_t a, uint32_t bytes) {
    asm volatile("mbarrier.arrive.expect_tx.shared.b64 _, [%0], %1;"
                 :: "r"(a), "r"(bytes) : "memory");
}

__device__ __forceinline__ void mbar_wait(uint32_t a, uint32_t parity) {
    asm volatile(
        "{\n\t.reg .pred P;\n\t"
        "W%=:\n\t"
        "mbarrier.try_wait.parity.shared.b64 P, [%0], %1;\n\t"
        "@P bra D%=;\n\t"
        "bra W%=;\n\t"
        "D%=:\n\t}"
        :: "r"(a), "r"(parity) : "memory");
}

__device__ __forceinline__ void bulk_g2s(uint32_t dst, const void* src,
                                         uint32_t bytes, uint32_t mb) {
    asm volatile(
        "cp.async.bulk.shared::cluster.global.mbarrier::complete_tx::bytes "
        "[%0], [%1], %2, [%3];"
        :: "r"(dst), "l"(src), "r"(bytes), "r"(mb) : "memory");
}

__device__ __forceinline__ void fence_proxy_async() {
    asm volatile("fence.proxy.async.shared::cta;" ::: "memory");
}

// ---------------------------------------------------------------------------
// Main GEMM (persistent): out[M,N] = fp16(X)@W + bias, fp32 accumulate
// Stage layout: A 16K @+0 | B 16K @+16384.  Ring continues across tiles.
// ---------------------------------------------------------------------------
__global__ void __launch_bounds__(NTHREADS, 2)
w2a16_gemm_kernel(const float* __restrict__ bias, float* __restrict__ out) {
    extern __shared__ char smem_raw[];
    uint32_t sb0 = smem_u32(smem_raw);
    uint32_t sb = (sb0 + 1023) & ~1023u;
    const uint32_t mbar = sb;                 // 3 x 8B mbarriers
    const uint32_t stage0 = sb + 1024;

    const int tid = threadIdx.x;
    const int wid = tid >> 5;
    const int lid = tid & 31;
    const int bid = blockIdx.x;

    const int warp_m = wid & 1;        // 0..1 -> m offset 64*warp_m
    const int warp_n = wid >> 1;       // 0..1 -> n offset 64*warp_n

    const char* xbase = reinterpret_cast<const char*>(g_Xh);
    const char* wbase = reinterpret_cast<const char*>(g_Wt);

    // Tiles for this CTA: bid, bid+296, ... ; raster (t&31)->m, (t>>5)->n
    const int ntiles = (NTILES - bid + GRIDSZ - 1) / GRIDSZ;  // 10 or 11
    const int total = ntiles * KITERS;                        // global iterations

    if (tid == 0) {
#pragma unroll
        for (int s = 0; s < STAGES; ++s) mbar_init(mbar + 8 * s, 1);
    }
    fence_proxy_async();
    __syncthreads();

    // Prologue fills: g = 0..2 (all within tile 0 since KITERS > STAGES)
    int tile0 = bid;
    int m0 = (tile0 & 31) * TM;
    int n0 = (tile0 >> 5) * TN;
    if (tid == 0) {
#pragma unroll
        for (int s = 0; s < STAGES; ++s) {
            const uint32_t st = stage0 + s * STAGE_BYTES;
            mbar_expect(mbar + 8 * s, STAGE_BYTES);
            bulk_g2s(st,         xbase + ((size_t)s * MDIM + m0) * 128, 16384, mbar + 8 * s);
            bulk_g2s(st + 16384, wbase + ((size_t)s * NDIM + n0) * 128, 16384, mbar + 8 * s);
        }
    }

    float acc[4][8][4];
#pragma unroll
    for (int i = 0; i < 4; ++i)
#pragma unroll
        for (int j = 0; j < 8; ++j)
#pragma unroll
            for (int c = 0; c < 4; ++c) acc[i][j][c] = 0.f;

    // Per-lane ldmatrix addressing components (row * 128B)
    const uint32_t rbA = (uint32_t)(warp_m * 64 + (lid & 15)) * 128;
    const uint32_t colA = (uint32_t)((lid >> 4) * 16);        // +8 halves
    const uint32_t rbB = (uint32_t)(warp_n * 64 + ((lid >> 4) & 1) * 8 + (lid & 7)) * 128;
    const uint32_t colB = (uint32_t)(((lid >> 3) & 1) * 16);  // +8 halves

    int s = 0, ph = 0;                  // rolling stage cursor: ph flips each ring wrap
    int tile = tile0;
    for (int g = 0; g < total; ++g) {
        const int k = g & (KITERS - 1);           // k within current tile
        const uint32_t stage_sm = stage0 + s * STAGE_BYTES;

        mbar_wait(mbar + 8 * s, ph);

#pragma unroll
        for (int ks = 0; ks < 4; ++ks) {
            const uint32_t kb = (uint32_t)ks * 32;   // 16 halves per k-step

            // A fragments: 4 x4-ldmatrix -> 4 m16-tiles
            uint32_t a[4][4];
#pragma unroll
            for (int mt = 0; mt < 4; ++mt) {
                uint32_t raw = rbA + (uint32_t)mt * 2048 + kb + colA;
                uint32_t addr = stage_sm + (raw ^ ((raw >> 3) & 0x70));
                asm volatile(
                    "ldmatrix.sync.aligned.m8n8.x4.shared.b16 {%0,%1,%2,%3}, [%4];"
                    : "=r"(a[mt][0]), "=r"(a[mt][1]), "=r"(a[mt][2]), "=r"(a[mt][3])
                    : "r"(addr));
            }

            // B fragments: 4 x4-ldmatrix -> 8 n8-tiles
            uint32_t b0[4], b1[4], b2[4], b3[4];
            uint32_t* bt[4] = {b0, b1, b2, b3};
#pragma unroll
            for (int t = 0; t < 4; ++t) {
                uint32_t raw = rbB + (uint32_t)t * 2048 + kb + colB;
                uint32_t addr = stage_sm + 16384 + (raw ^ ((raw >> 3) & 0x70));
                asm volatile(
                    "ldmatrix.sync.aligned.m8n8.x4.shared.b16 {%0,%1,%2,%3}, [%4];"
                    : "=r"(bt[t][0]), "=r"(bt[t][1]), "=r"(bt[t][2]), "=r"(bt[t][3])
                    : "r"(addr));
            }

            // 32 MMAs per fragment set (ratio 4 MMA:LDSM)
#pragma unroll
            for (int mt = 0; mt < 4; ++mt) {
#pragma unroll
                for (int t = 0; t < 4; ++t) {
#pragma unroll
                    for (int half = 0; half < 2; ++half) {
                        const int ni = t * 2 + half;
                        float* c = acc[mt][ni];
                        uint32_t bb0 = bt[t][half * 2];
                        uint32_t bb1 = bt[t][half * 2 + 1];
                        asm volatile(
                            "mma.sync.aligned.m16n8k16.row.col.f32.f16.f16.f32 "
                            "{%0,%1,%2,%3}, {%4,%5,%6,%7}, {%8,%9}, {%0,%1,%2,%3};"
                            : "+f"(c[0]), "+f"(c[1]), "+f"(c[2]), "+f"(c[3])
                            : "r"(a[mt][0]), "r"(a[mt][1]), "r"(a[mt][2]), "r"(a[mt][3]),
                              "r"(bb0), "r"(bb1));
                    }
                }
            }
        }

        __syncthreads();   // all LDS reads of stage s done before refill

        // Refill this ring slot for global iteration g+3 (may be next tile)
        const int gf = g + STAGES;
        if (gf < total && tid == 0) {
            const int tf = bid + GRIDSZ * (gf >> 6);   // tile of fill
            const int kf = gf & (KITERS - 1);
            const int m0f = (tf & 31) * TM;
            const int n0f = (tf >> 5) * TN;
            mbar_expect(mbar + 8 * s, STAGE_BYTES);
            bulk_g2s(stage_sm,         xbase + ((size_t)kf * MDIM + m0f) * 128, 16384, mbar + 8 * s);
            bulk_g2s(stage_sm + 16384, wbase + ((size_t)kf * NDIM + n0f) * 128, 16384, mbar + 8 * s);
        }

        // Tile finished: epilogue from registers (no sync needed), reset acc
        if (k == KITERS - 1) {
            const int mrow0 = m0 + warp_m * 64 + (lid >> 2);
            const int ncol0 = n0 + warp_n * 64 + (lid & 3) * 2;
#pragma unroll
            for (int mt = 0; mt < 4; ++mt) {
#pragma unroll
                for (int ni = 0; ni < 8; ++ni) {
                    const int n = ncol0 + ni * 8;
                    const float bx = bias[n];
                    const float by = bias[n + 1];
                    const int mA = mrow0 + mt * 16;
                    float2 v0 = {acc[mt][ni][0] + bx, acc[mt][ni][1] + by};
                    float2 v1 = {acc[mt][ni][2] + bx, acc[mt][ni][3] + by};
                    *reinterpret_cast<float2*>(out + (size_t)mA * NDIM + n) = v0;
                    *reinterpret_cast<float2*>(out + (size_t)(mA + 8) * NDIM + n) = v1;
                }
            }
#pragma unroll
            for (int i = 0; i < 4; ++i)
#pragma unroll
                for (int j = 0; j < 8; ++j)
#pragma unroll
                    for (int c = 0; c < 4; ++c) acc[i][j][c] = 0.f;
            tile += GRIDSZ;
            m0 = (tile & 31) * TM;
            n0 = (tile >> 5) * TN;
        }

        if (++s == STAGES) { s = 0; ph ^= 1; }
    }
}

// ---------------------------------------------------------------------------
// Launch
// ---------------------------------------------------------------------------
extern "C" void kernel_launch(void* const* d_in, const int* in_sizes, int n_in,
                              void* d_out, int out_size) {
    (void)in_sizes; (void)n_in; (void)out_size;
    const float* input   = (const float*)d_in[0];
    const int*   qweight = (const int*)d_in[1];
    const float* scale   = (const float*)d_in[2];
    const float* zp      = (const float*)d_in[3];
    const float* bias    = (const float*)d_in[4];
    float* out = (float*)d_out;

    cudaFuncSetAttribute(w2a16_gemm_kernel,
                         cudaFuncAttributeMaxDynamicSharedMemorySize, SMEM_TOTAL);

    prof_pad_kernel<<<1, 32>>>();   // rotate ncu capture slot
    tile_x_kernel<<<(unsigned)((size_t)MDIM * KDIM / 8 / 256), 256>>>(
        reinterpret_cast<const float4*>(input));
    dequant_kernel<<<dim3(NDIM / 32, KDIM / 32), dim3(32, 8)>>>(qweight, scale, zp);
    w2a16_gemm_kernel<<<GRIDSZ, NTHREADS, SMEM_TOTAL>>>(bias, out);
}

// round 14
// speedup vs baseline: 1.0707x; 1.0707x over previous
#include <cuda_runtime.h>
#include <cuda_fp16.h>
#include <cstdint>
#include <cstddef>

// ---------------------------------------------------------------------------
// Problem constants
// ---------------------------------------------------------------------------
#define MDIM 4096
#define KDIM 4096
#define NDIM 12288
// GROUP = 64

// GEMM tiling (byte-identical to the 856us R11 engine): CTA 128x128, TK=64,
// 4 warps (2m x 2n, warp tile 64x64), 3 stages x 32KB, bulk-async fills,
// ratio 4 MMA:LDSM, 2 CTAs/SM, __syncthreads pipeline.
#define TM 128
#define TN 128
#define TKC 64
#define STAGES 3
#define KITERS (KDIM / TKC)           // 64
#define TILES_M (MDIM / TM)           // 32
#define TILES_N (NDIM / TN)           // 96
#define STAGE_BYTES 32768             // A 16K + B 16K
#define NTHREADS 128
#define SMEM_TOTAL (1024 + STAGES * STAGE_BYTES)   // 99328 -> 2 CTAs/SM

// ---------------------------------------------------------------------------
// Scratch (device globals: no allocation allowed)
// g_Xh: X in fp16, 64-k-chunk tiled + swizzled: [kc][m][8 chunks of 16B],
//       chunk c of row m stored at position (c ^ (m&7)).
// g_Wt: W^T in fp16, same tiled+swizzled layout over n: [kc][n][8 chunks].
// ---------------------------------------------------------------------------
__device__ __half g_Xh[(size_t)MDIM * KDIM];   // 32 MB
__device__ __half g_Wt[(size_t)NDIM * KDIM];   // 96 MB

// ---------------------------------------------------------------------------
// Prepass 1: fp16 X -> tiled+swizzled layout. One 16B chunk per thread.
// ---------------------------------------------------------------------------
__global__ void __launch_bounds__(256) tile_x_kernel(const float4* __restrict__ x) {
    const size_t i = (size_t)blockIdx.x * 256 + threadIdx.x;  // chunk id, M*K/8 total
    const int m  = (int)(i >> 9);      // K/8 = 512 chunks per row
    const int c8 = (int)(i & 511);
    const int kc = c8 >> 3;
    const int c  = c8 & 7;
    float4 v0 = x[(size_t)m * 1024 + c8 * 2];
    float4 v1 = x[(size_t)m * 1024 + c8 * 2 + 1];
    __half2 h0 = __floats2half2_rn(v0.x, v0.y);
    __half2 h1 = __floats2half2_rn(v0.z, v0.w);
    __half2 h2 = __floats2half2_rn(v1.x, v1.y);
    __half2 h3 = __floats2half2_rn(v1.z, v1.w);
    uint4 p;
    p.x = reinterpret_cast<uint32_t&>(h0);
    p.y = reinterpret_cast<uint32_t&>(h1);
    p.z = reinterpret_cast<uint32_t&>(h2);
    p.w = reinterpret_cast<uint32_t&>(h3);
    const size_t idx16 = ((size_t)kc * MDIM + m) * 8 + (c ^ (m & 7));
    reinterpret_cast<uint4*>(g_Xh)[idx16] = p;
}

// ---------------------------------------------------------------------------
// Prepass 2: dequant q[K,N] (codes 0..3) -> fp16 W^T tiled+swizzled.
// w[k,n] = q[k,n]*scale[k/64,n] + zp[k/64,n]
// Tile: 64 k (one kc chunk, one quant group) x 32 n. 256 threads.
// Phase 1: coalesced q reads, dequant into SMEM tile [n][k] (padded).
// Phase 2: one thread per 16B output chunk, warp writes 512B contiguous.
// ---------------------------------------------------------------------------
__global__ void __launch_bounds__(256) dequant_kernel(const int* __restrict__ q,
                                                      const float* __restrict__ scale,
                                                      const float* __restrict__ zp) {
    __shared__ __half tile[32][72];    // [n_local][k_local], row stride 144B (16B-aligned)
    const int n0 = blockIdx.x * 32;
    const int kc = blockIdx.y;         // k0 = kc*64, exactly one group
    const int k0 = kc * 64;
    const int tx = threadIdx.x & 31;   // n lane
    const int ty = threadIdx.x >> 5;   // 0..7

    const float s = scale[(size_t)kc * NDIM + n0 + tx];
    const float z = zp[(size_t)kc * NDIM + n0 + tx];
#pragma unroll
    for (int r = 0; r < 8; ++r) {
        const int kl = ty + r * 8;
        const int qq = q[(size_t)(k0 + kl) * NDIM + n0 + tx];
        tile[tx][kl] = __float2half((float)qq * s + z);
    }
    __syncthreads();

    // Phase 2: thread t -> (n_local = t>>3, c_store = t&7)
    const int t = threadIdx.x;
    const int n_local = t >> 3;
    const int c_store = t & 7;
    const int n = n0 + n_local;
    const int c_src = c_store ^ (n & 7);
    const uint4 v = *reinterpret_cast<const uint4*>(&tile[n_local][c_src * 8]);
    reinterpret_cast<uint4*>(g_Wt)[((size_t)kc * NDIM + n) * 8 + c_store] = v;
}

// ---------------------------------------------------------------------------
// PTX helpers (sm_90-standard, compute_103-safe)
// ---------------------------------------------------------------------------
__device__ __forceinline__ uint32_t smem_u32(const void* p) {
    uint32_t a;
    asm("{ .reg .u64 t; cvta.to.shared.u64 t, %1; cvt.u32.u64 %0, t; }" : "=r"(a) : "l"(p));
    return a;
}

__device__ __forceinline__ void mbar_init(uint32_t a, uint32_t cnt) {
    asm volatile("mbarrier.init.shared.b64 [%0], %1;" :: "r"(a), "r"(cnt) : "memory");
}

__device__ __forceinline__ void mbar_expect(uint32_t a, uint32_t bytes) {
    asm volatile("mbarrier.arrive.expect_tx.shared.b64 _, [%0], %1;"
                 :: "r"(a), "r"(bytes) : "memory");
}

__device__ __forceinline__ void mbar_wait(uint32_t a, uint32_t parity) {
    asm volatile(
        "{\n\t.reg .pred P;\n\t"
        "W%=:\n\t"
        "mbarrier.try_wait.parity.shared.b64 P, [%0], %1;\n\t"
        "@P bra D%=;\n\t"
        "bra W%=;\n\t"
        "D%=:\n\t}"
        :: "r"(a), "r"(parity) : "memory");
}

__device__ __forceinline__ void bulk_g2s(uint32_t dst, const void* src,
                                         uint32_t bytes, uint32_t mb) {
    asm volatile(
        "cp.async.bulk.shared::cluster.global.mbarrier::complete_tx::bytes "
        "[%0], [%1], %2, [%3];"
        :: "r"(dst), "l"(src), "r"(bytes), "r"(mb) : "memory");
}

__device__ __forceinline__ void fence_proxy_async() {
    asm volatile("fence.proxy.async.shared::cta;" ::: "memory");
}

// ---------------------------------------------------------------------------
// Main GEMM: out[M,N] = fp16(X)@W + bias, fp32 accumulate
// Stage layout: A 16K @+0 | B 16K @+16384
// ---------------------------------------------------------------------------
__global__ void __launch_bounds__(NTHREADS, 2)
w2a16_gemm_kernel(const float* __restrict__ bias, float* __restrict__ out) {
    extern __shared__ char smem_raw[];
    uint32_t sb0 = smem_u32(smem_raw);
    uint32_t sb = (sb0 + 1023) & ~1023u;
    const uint32_t mbar = sb;                 // 3 x 8B mbarriers
    const uint32_t stage0 = sb + 1024;

    const int tid = threadIdx.x;
    const int wid = tid >> 5;
    const int lid = tid & 31;

    // Raster: 32 consecutive bids form one full-M column sharing a W slab
    const int bid = blockIdx.x;
    const int m0 = (bid & 31) * TM;
    const int n0 = (bid >> 5) * TN;

    const int warp_m = wid & 1;        // 0..1 -> m offset 64*warp_m
    const int warp_n = wid >> 1;       // 0..1 -> n offset 64*warp_n

    const char* xbase = reinterpret_cast<const char*>(g_Xh);
    const char* wbase = reinterpret_cast<const char*>(g_Wt);

    if (tid == 0) {
#pragma unroll
        for (int s = 0; s < STAGES; ++s) mbar_init(mbar + 8 * s, 1);
    }
    fence_proxy_async();
    __syncthreads();

    // Prologue fills: 2 bulk ops per stage (A 16K, B 16K)
    if (tid == 0) {
#pragma unroll
        for (int s = 0; s < STAGES; ++s) {
            const uint32_t st = stage0 + s * STAGE_BYTES;
            mbar_expect(mbar + 8 * s, STAGE_BYTES);
            bulk_g2s(st,         xbase + ((size_t)s * MDIM + m0) * 128, 16384, mbar + 8 * s);
            bulk_g2s(st + 16384, wbase + ((size_t)s * NDIM + n0) * 128, 16384, mbar + 8 * s);
        }
    }

    float acc[4][8][4];
#pragma unroll
    for (int i = 0; i < 4; ++i)
#pragma unroll
        for (int j = 0; j < 8; ++j)
#pragma unroll
            for (int c = 0; c < 4; ++c) acc[i][j][c] = 0.f;

    // Per-lane ldmatrix addressing components (row * 128B)
    const uint32_t rbA = (uint32_t)(warp_m * 64 + (lid & 15)) * 128;
    const uint32_t colA = (uint32_t)((lid >> 4) * 16);        // +8 halves
    const uint32_t rbB = (uint32_t)(warp_n * 64 + ((lid >> 4) & 1) * 8 + (lid & 7)) * 128;
    const uint32_t colB = (uint32_t)(((lid >> 3) & 1) * 16);  // +8 halves

    int s = 0, ph = 0;                  // rolling stage cursor (3 = non-pow2)
    for (int k = 0; k < KITERS; ++k) {
        const uint32_t stage_sm = stage0 + s * STAGE_BYTES;

        mbar_wait(mbar + 8 * s, ph);

#pragma unroll
        for (int ks = 0; ks < 4; ++ks) {
            const uint32_t kb = (uint32_t)ks * 32;   // 16 halves per k-step

            // A fragments: 4 x4-ldmatrix -> 4 m16-tiles
            uint32_t a[4][4];
#pragma unroll
            for (int mt = 0; mt < 4; ++mt) {
                uint32_t raw = rbA + (uint32_t)mt * 2048 + kb + colA;
                uint32_t addr = stage_sm + (raw ^ ((raw >> 3) & 0x70));
                asm volatile(
                    "ldmatrix.sync.aligned.m8n8.x4.shared.b16 {%0,%1,%2,%3}, [%4];"
                    : "=r"(a[mt][0]), "=r"(a[mt][1]), "=r"(a[mt][2]), "=r"(a[mt][3])
                    : "r"(addr));
            }

            // B fragments: 4 x4-ldmatrix -> 8 n8-tiles
            uint32_t b0[4], b1[4], b2[4], b3[4];
            uint32_t* bt[4] = {b0, b1, b2, b3};
#pragma unroll
            for (int t = 0; t < 4; ++t) {
                uint32_t raw = rbB + (uint32_t)t * 2048 + kb + colB;
                uint32_t addr = stage_sm + 16384 + (raw ^ ((raw >> 3) & 0x70));
                asm volatile(
                    "ldmatrix.sync.aligned.m8n8.x4.shared.b16 {%0,%1,%2,%3}, [%4];"
                    : "=r"(bt[t][0]), "=r"(bt[t][1]), "=r"(bt[t][2]), "=r"(bt[t][3])
                    : "r"(addr));
            }

            // 32 MMAs per fragment set (ratio 4 MMA:LDSM)
#pragma unroll
            for (int mt = 0; mt < 4; ++mt) {
#pragma unroll
                for (int t = 0; t < 4; ++t) {
#pragma unroll
                    for (int half = 0; half < 2; ++half) {
                        const int ni = t * 2 + half;
                        float* c = acc[mt][ni];
                        uint32_t bb0 = bt[t][half * 2];
                        uint32_t bb1 = bt[t][half * 2 + 1];
                        asm volatile(
                            "mma.sync.aligned.m16n8k16.row.col.f32.f16.f16.f32 "
                            "{%0,%1,%2,%3}, {%4,%5,%6,%7}, {%8,%9}, {%0,%1,%2,%3};"
                            : "+f"(c[0]), "+f"(c[1]), "+f"(c[2]), "+f"(c[3])
                            : "r"(a[mt][0]), "r"(a[mt][1]), "r"(a[mt][2]), "r"(a[mt][3]),
                              "r"(bb0), "r"(bb1));
                    }
                }
            }
        }

        __syncthreads();   // all LDS reads of stage s done before refill

        const int nk = k + STAGES;
        if (nk < KITERS && tid == 0) {
            const uint32_t st = stage_sm;
            mbar_expect(mbar + 8 * s, STAGE_BYTES);
            bulk_g2s(st,         xbase + ((size_t)nk * MDIM + m0) * 128, 16384, mbar + 8 * s);
            bulk_g2s(st + 16384, wbase + ((size_t)nk * NDIM + n0) * 128, 16384, mbar + 8 * s);
        }

        if (++s == STAGES) { s = 0; ph ^= 1; }
    }

    // Epilogue: out = acc + bias
    const int mrow0 = m0 + warp_m * 64 + (lid >> 2);
    const int ncol0 = n0 + warp_n * 64 + (lid & 3) * 2;
#pragma unroll
    for (int mt = 0; mt < 4; ++mt) {
#pragma unroll
        for (int ni = 0; ni < 8; ++ni) {
            const int n = ncol0 + ni * 8;
            const float bx = bias[n];
            const float by = bias[n + 1];
            const int mA = mrow0 + mt * 16;
            float2 v0 = {acc[mt][ni][0] + bx, acc[mt][ni][1] + by};
            float2 v1 = {acc[mt][ni][2] + bx, acc[mt][ni][3] + by};
            *reinterpret_cast<float2*>(out + (size_t)mA * NDIM + n) = v0;
            *reinterpret_cast<float2*>(out + (size_t)(mA + 8) * NDIM + n) = v1;
        }
    }
}

// ---------------------------------------------------------------------------
// Launch
// ---------------------------------------------------------------------------
extern "C" void kernel_launch(void* const* d_in, const int* in_sizes, int n_in,
                              void* d_out, int out_size) {
    (void)in_sizes; (void)n_in; (void)out_size;
    const float* input   = (const float*)d_in[0];
    const int*   qweight = (const int*)d_in[1];
    const float* scale   = (const float*)d_in[2];
    const float* zp      = (const float*)d_in[3];
    const float* bias    = (const float*)d_in[4];
    float* out = (float*)d_out;

    cudaFuncSetAttribute(w2a16_gemm_kernel,
                         cudaFuncAttributeMaxDynamicSharedMemorySize, SMEM_TOTAL);

    tile_x_kernel<<<(unsigned)((size_t)MDIM * KDIM / 8 / 256), 256>>>(
        reinterpret_cast<const float4*>(input));
    dequant_kernel<<<dim3(NDIM / 32, KDIM / 64), 256>>>(qweight, scale, zp);
    w2a16_gemm_kernel<<<TILES_M * TILES_N, NTHREADS, SMEM_TOTAL>>>(bias, out);
}

// round 16
// speedup vs baseline: 1.0751x; 1.0041x over previous
#include <cuda_runtime.h>
#include <cuda_fp16.h>
#include <cstdint>
#include <cstddef>

// ---------------------------------------------------------------------------
// Problem constants
// ---------------------------------------------------------------------------
#define MDIM 4096
#define KDIM 4096
#define NDIM 12288
// GROUP = 64

// GEMM tiling (R11/R14 engine, proven): CTA 128x128, TK=64, 4 warps
// (2m x 2n, warp tile 64x64), 3 stages x 32KB, bulk-async fills,
// ratio 4 MMA:LDSM, 2 CTAs/SM, barrier AFTER MMAs (cross-proxy safe).
#define TM 128
#define TN 128
#define TKC 64
#define STAGES 3
#define KITERS (KDIM / TKC)           // 64
#define TILES_M (MDIM / TM)           // 32
#define TILES_N (NDIM / TN)           // 96
#define STAGE_BYTES 32768             // A 16K + B 16K
#define NTHREADS 128
#define SMEM_TOTAL (1024 + STAGES * STAGE_BYTES)   // 99328 -> 2 CTAs/SM

// Merged prepass grid split
#define TILEX_BLOCKS 8192             // M*K/8 chunks / 256
#define DEQ_NB (NDIM / 32)            // 384
#define DEQ_KB (KDIM / 64)            // 64
#define PREP_BLOCKS (TILEX_BLOCKS + DEQ_NB * DEQ_KB)

// ---------------------------------------------------------------------------
// Scratch (device globals: no allocation allowed)
// g_Xh: X in fp16, 64-k-chunk tiled + swizzled: [kc][m][8 chunks of 16B],
//       chunk c of row m stored at position (c ^ (m&7)).
// g_Wt: W^T in fp16, same tiled+swizzled layout over n: [kc][n][8 chunks].
// ---------------------------------------------------------------------------
__device__ __half g_Xh[(size_t)MDIM * KDIM];   // 32 MB
__device__ __half g_Wt[(size_t)NDIM * KDIM];   // 96 MB

// ---------------------------------------------------------------------------
// Merged prepass: blocks [0, TILEX_BLOCKS) do X conversion; the rest dequant.
// ---------------------------------------------------------------------------
__global__ void __launch_bounds__(256) prepass_kernel(const float4* __restrict__ x,
                                                      const int* __restrict__ q,
                                                      const float* __restrict__ scale,
                                                      const float* __restrict__ zp) {
    if (blockIdx.x < TILEX_BLOCKS) {
        // ---- tile_x: fp16 X -> tiled+swizzled, one 16B chunk per thread ----
        const size_t i = (size_t)blockIdx.x * 256 + threadIdx.x;
        const int m  = (int)(i >> 9);      // K/8 = 512 chunks per row
        const int c8 = (int)(i & 511);
        const int kc = c8 >> 3;
        const int c  = c8 & 7;
        float4 v0 = x[(size_t)m * 1024 + c8 * 2];
        float4 v1 = x[(size_t)m * 1024 + c8 * 2 + 1];
        __half2 h0 = __floats2half2_rn(v0.x, v0.y);
        __half2 h1 = __floats2half2_rn(v0.z, v0.w);
        __half2 h2 = __floats2half2_rn(v1.x, v1.y);
        __half2 h3 = __floats2half2_rn(v1.z, v1.w);
        uint4 p;
        p.x = reinterpret_cast<uint32_t&>(h0);
        p.y = reinterpret_cast<uint32_t&>(h1);
        p.z = reinterpret_cast<uint32_t&>(h2);
        p.w = reinterpret_cast<uint32_t&>(h3);
        const size_t idx16 = ((size_t)kc * MDIM + m) * 8 + (c ^ (m & 7));
        reinterpret_cast<uint4*>(g_Xh)[idx16] = p;
    } else {
        // ---- dequant: q[K,N] codes -> fp16 W^T tiled+swizzled ----
        // Tile: 64 k (one group) x 32 n. Phase 1 coalesced reads -> SMEM;
        // phase 2: one 16B swizzled chunk per thread, 512B contiguous per warp.
        __shared__ __half tile[32][72];    // [n_local][k_local], 144B row stride
        const int pb = blockIdx.x - TILEX_BLOCKS;
        const int n0 = (pb % DEQ_NB) * 32;
        const int kc = pb / DEQ_NB;
        const int k0 = kc * 64;
        const int tx = threadIdx.x & 31;   // n lane
        const int ty = threadIdx.x >> 5;   // 0..7

        const float s = scale[(size_t)kc * NDIM + n0 + tx];
        const float z = zp[(size_t)kc * NDIM + n0 + tx];
#pragma unroll
        for (int r = 0; r < 8; ++r) {
            const int kl = ty + r * 8;
            const int qq = q[(size_t)(k0 + kl) * NDIM + n0 + tx];
            tile[tx][kl] = __float2half((float)qq * s + z);
        }
        __syncthreads();

        const int t = threadIdx.x;
        const int n_local = t >> 3;
        const int c_store = t & 7;
        const int n = n0 + n_local;
        const int c_src = c_store ^ (n & 7);
        const uint4 v = *reinterpret_cast<const uint4*>(&tile[n_local][c_src * 8]);
        reinterpret_cast<uint4*>(g_Wt)[((size_t)kc * NDIM + n) * 8 + c_store] = v;
    }
}

// ---------------------------------------------------------------------------
// PTX helpers (sm_90-standard, compute_103-safe)
// ---------------------------------------------------------------------------
__device__ __forceinline__ uint32_t smem_u32(const void* p) {
    uint32_t a;
    asm("{ .reg .u64 t; cvta.to.shared.u64 t, %1; cvt.u32.u64 %0, t; }" : "=r"(a) : "l"(p));
    return a;
}

__device__ __forceinline__ void mbar_init(uint32_t a, uint32_t cnt) {
    asm volatile("mbarrier.init.shared.b64 [%0], %1;" :: "r"(a), "r"(cnt) : "memory");
}

__device__ __forceinline__ void mbar_expect(uint32_t a, uint32_t bytes) {
    asm volatile("mbarrier.arrive.expect_tx.shared.b64 _, [%0], %1;"
                 :: "r"(a), "r"(bytes) : "memory");
}

__device__ __forceinline__ void mbar_wait(uint32_t a, uint32_t parity) {
    asm volatile(
        "{\n\t.reg .pred P;\n\t"
        "W%=:\n\t"
        "mbarrier.try_wait.parity.shared.b64 P, [%0], %1;\n\t"
        "@P bra D%=;\n\t"
        "bra W%=;\n\t"
        "D%=:\n\t}"
        :: "r"(a), "r"(parity) : "memory");
}

__device__ __forceinline__ void bulk_g2s(uint32_t dst, const void* src,
                                         uint32_t bytes, uint32_t mb) {
    asm volatile(
        "cp.async.bulk.shared::cluster.global.mbarrier::complete_tx::bytes "
        "[%0], [%1], %2, [%3];"
        :: "r"(dst), "l"(src), "r"(bytes), "r"(mb) : "memory");
}

__device__ __forceinline__ void fence_proxy_async() {
    asm volatile("fence.proxy.async.shared::cta;" ::: "memory");
}

// ---------------------------------------------------------------------------
// Main GEMM: out[M,N] = fp16(X)@W + bias, fp32 accumulate
// Stage layout: A 16K @+0 | B 16K @+16384
// ---------------------------------------------------------------------------
__global__ void __launch_bounds__(NTHREADS, 2)
w2a16_gemm_kernel(const float* __restrict__ bias, float* __restrict__ out) {
    extern __shared__ char smem_raw[];
    uint32_t sb0 = smem_u32(smem_raw);
    uint32_t sb = (sb0 + 1023) & ~1023u;
    const uint32_t mbar = sb;                 // 3 x 8B mbarriers
    const uint32_t stage0 = sb + 1024;

    const int tid = threadIdx.x;
    const int wid = tid >> 5;
    const int lid = tid & 31;

    // Raster: 32 consecutive bids form one full-M column sharing a W slab
    const int bid = blockIdx.x;
    const int m0 = (bid & 31) * TM;
    const int n0 = (bid >> 5) * TN;

    const int warp_m = wid & 1;        // 0..1 -> m offset 64*warp_m
    const int warp_n = wid >> 1;       // 0..1 -> n offset 64*warp_n

    const char* xbase = reinterpret_cast<const char*>(g_Xh);
    const char* wbase = reinterpret_cast<const char*>(g_Wt);

    if (tid == 0) {
#pragma unroll
        for (int s = 0; s < STAGES; ++s) mbar_init(mbar + 8 * s, 1);
    }
    fence_proxy_async();
    __syncthreads();

    // Prologue fills: 2 bulk ops per stage (A 16K, B 16K)
    if (tid == 0) {
#pragma unroll
        for (int s = 0; s < STAGES; ++s) {
            const uint32_t st = stage0 + s * STAGE_BYTES;
            mbar_expect(mbar + 8 * s, STAGE_BYTES);
            bulk_g2s(st,         xbase + ((size_t)s * MDIM + m0) * 128, 16384, mbar + 8 * s);
            bulk_g2s(st + 16384, wbase + ((size_t)s * NDIM + n0) * 128, 16384, mbar + 8 * s);
        }
    }

    float acc[4][8][4];
#pragma unroll
    for (int i = 0; i < 4; ++i)
#pragma unroll
        for (int j = 0; j < 8; ++j)
#pragma unroll
            for (int c = 0; c < 4; ++c) acc[i][j][c] = 0.f;

    // Per-lane ldmatrix addressing components (row * 128B)
    const uint32_t rbA = (uint32_t)(warp_m * 64 + (lid & 15)) * 128;
    const uint32_t colA = (uint32_t)((lid >> 4) * 16);        // +8 halves
    const uint32_t rbB = (uint32_t)(warp_n * 64 + ((lid >> 4) & 1) * 8 + (lid & 7)) * 128;
    const uint32_t colB = (uint32_t)(((lid >> 3) & 1) * 16);  // +8 halves

    int s = 0, ph = 0;                  // rolling stage cursor (3 = non-pow2)
    for (int k = 0; k < KITERS; ++k) {
        const uint32_t stage_sm = stage0 + s * STAGE_BYTES;

        mbar_wait(mbar + 8 * s, ph);

#pragma unroll
        for (int ks = 0; ks < 4; ++ks) {
            const uint32_t kb = (uint32_t)ks * 32;   // 16 halves per k-step

            // A fragments: 4 x4-ldmatrix -> 4 m16-tiles
            uint32_t a[4][4];
#pragma unroll
            for (int mt = 0; mt < 4; ++mt) {
                uint32_t raw = rbA + (uint32_t)mt * 2048 + kb + colA;
                uint32_t addr = stage_sm + (raw ^ ((raw >> 3) & 0x70));
                asm volatile(
                    "ldmatrix.sync.aligned.m8n8.x4.shared.b16 {%0,%1,%2,%3}, [%4];"
                    : "=r"(a[mt][0]), "=r"(a[mt][1]), "=r"(a[mt][2]), "=r"(a[mt][3])
                    : "r"(addr));
            }

            // B fragments: 4 x4-ldmatrix -> 8 n8-tiles
            uint32_t b0[4], b1[4], b2[4], b3[4];
            uint32_t* bt[4] = {b0, b1, b2, b3};
#pragma unroll
            for (int t = 0; t < 4; ++t) {
                uint32_t raw = rbB + (uint32_t)t * 2048 + kb + colB;
                uint32_t addr = stage_sm + 16384 + (raw ^ ((raw >> 3) & 0x70));
                asm volatile(
                    "ldmatrix.sync.aligned.m8n8.x4.shared.b16 {%0,%1,%2,%3}, [%4];"
                    : "=r"(bt[t][0]), "=r"(bt[t][1]), "=r"(bt[t][2]), "=r"(bt[t][3])
                    : "r"(addr));
            }

            // 32 MMAs per fragment set (ratio 4 MMA:LDSM)
#pragma unroll
            for (int mt = 0; mt < 4; ++mt) {
#pragma unroll
                for (int t = 0; t < 4; ++t) {
#pragma unroll
                    for (int half = 0; half < 2; ++half) {
                        const int ni = t * 2 + half;
                        float* c = acc[mt][ni];
                        uint32_t bb0 = bt[t][half * 2];
                        uint32_t bb1 = bt[t][half * 2 + 1];
                        asm volatile(
                            "mma.sync.aligned.m16n8k16.row.col.f32.f16.f16.f32 "
                            "{%0,%1,%2,%3}, {%4,%5,%6,%7}, {%8,%9}, {%0,%1,%2,%3};"
                            : "+f"(c[0]), "+f"(c[1]), "+f"(c[2]), "+f"(c[3])
                            : "r"(a[mt][0]), "r"(a[mt][1]), "r"(a[mt][2]), "r"(a[mt][3]),
                              "r"(bb0), "r"(bb1));
                    }
                }
            }
        }

        __syncthreads();   // all LDS reads of stage s consumed before refill
                           // (MMAs before barrier force ldmatrix completion —
                           //  required for cross-proxy safety vs TMA write)

        const int nk = k + STAGES;
        if (nk < KITERS && tid == 0) {
            const uint32_t st = stage_sm;
            mbar_expect(mbar + 8 * s, STAGE_BYTES);
            bulk_g2s(st,         xbase + ((size_t)nk * MDIM + m0) * 128, 16384, mbar + 8 * s);
            bulk_g2s(st + 16384, wbase + ((size_t)nk * NDIM + n0) * 128, 16384, mbar + 8 * s);
        }

        if (++s == STAGES) { s = 0; ph ^= 1; }
    }

    // Epilogue: out = acc + bias
    const int mrow0 = m0 + warp_m * 64 + (lid >> 2);
    const int ncol0 = n0 + warp_n * 64 + (lid & 3) * 2;
#pragma unroll
    for (int mt = 0; mt < 4; ++mt) {
#pragma unroll
        for (int ni = 0; ni < 8; ++ni) {
            const int n = ncol0 + ni * 8;
            const float bx = bias[n];
            const float by = bias[n + 1];
            const int mA = mrow0 + mt * 16;
            float2 v0 = {acc[mt][ni][0] + bx, acc[mt][ni][1] + by};
            float2 v1 = {acc[mt][ni][2] + bx, acc[mt][ni][3] + by};
            *reinterpret_cast<float2*>(out + (size_t)mA * NDIM + n) = v0;
            *reinterpret_cast<float2*>(out + (size_t)(mA + 8) * NDIM + n) = v1;
        }
    }
}

// ---------------------------------------------------------------------------
// Launch
// ---------------------------------------------------------------------------
extern "C" void kernel_launch(void* const* d_in, const int* in_sizes, int n_in,
                              void* d_out, int out_size) {
    (void)in_sizes; (void)n_in; (void)out_size;
    const float* input   = (const float*)d_in[0];
    const int*   qweight = (const int*)d_in[1];
    const float* scale   = (const float*)d_in[2];
    const float* zp      = (const float*)d_in[3];
    const float* bias    = (const float*)d_in[4];
    float* out = (float*)d_out;

    cudaFuncSetAttribute(w2a16_gemm_kernel,
                         cudaFuncAttributeMaxDynamicSharedMemorySize, SMEM_TOTAL);

    prepass_kernel<<<PREP_BLOCKS, 256>>>(
        reinterpret_cast<const float4*>(input), qweight, scale, zp);
    w2a16_gemm_kernel<<<TILES_M * TILES_N, NTHREADS, SMEM_TOTAL>>>(bias, out);
}

// round 17
// speedup vs baseline: 1.1026x; 1.0256x over previous
#include <cuda_runtime.h>
#include <cuda_fp16.h>
#include <cstdint>
#include <cstddef>

// ---------------------------------------------------------------------------
// Problem constants
// ---------------------------------------------------------------------------
#define MDIM 4096
#define KDIM 4096
#define NDIM 12288
// GROUP = 64

// GEMM tiling (R16 engine): CTA 128x128, TK=64, 4 warps (2m x 2n, warp tile
// 64x64), 3 stages x 32KB, bulk-async fills, ratio 4 MMA:LDSM, 2 CTAs/SM.
// R17: wave-tail split-K — 2960 full-K CTAs (10 exact waves) + last 112 tiles
// as 224 half-K CTAs with ordered flag-based combine (deterministic).
#define TM 128
#define TN 128
#define TKC 64
#define STAGES 3
#define KITERS (KDIM / TKC)           // 64
#define TILES_M (MDIM / TM)           // 32
#define TILES_N (NDIM / TN)           // 96
#define NTILES (TILES_M * TILES_N)    // 3072
#define FULL_TILES 2960               // 10 exact waves at 2 CTAs/SM x 148 SMs
#define TAIL_TILES (NTILES - FULL_TILES)   // 112
#define GRIDSZ (FULL_TILES + 2 * TAIL_TILES)  // 3184
#define STAGE_BYTES 32768             // A 16K + B 16K
#define NTHREADS 128
#define SMEM_TOTAL (1024 + STAGES * STAGE_BYTES)   // 99328 -> 2 CTAs/SM

// Merged prepass grid split
#define TILEX_BLOCKS 8192             // M*K/8 chunks / 256
#define DEQ_NB (NDIM / 32)            // 384
#define DEQ_KB (KDIM / 64)            // 64
#define PREP_BLOCKS (TILEX_BLOCKS + DEQ_NB * DEQ_KB)

// ---------------------------------------------------------------------------
// Scratch (device globals: no allocation allowed)
// ---------------------------------------------------------------------------
__device__ __half g_Xh[(size_t)MDIM * KDIM];   // 32 MB
__device__ __half g_Wt[(size_t)NDIM * KDIM];   // 96 MB
__device__ unsigned g_flags[TAIL_TILES];       // tail pair flags (prepass zeroes)

// ---------------------------------------------------------------------------
// Merged prepass: blocks [0, TILEX_BLOCKS) do X conversion; the rest dequant.
// Block 0 additionally zeroes the tail-pair flags (stream-ordered vs GEMM).
// ---------------------------------------------------------------------------
__global__ void __launch_bounds__(256) prepass_kernel(const float4* __restrict__ x,
                                                      const int* __restrict__ q,
                                                      const float* __restrict__ scale,
                                                      const float* __restrict__ zp) {
    if (blockIdx.x == 0 && threadIdx.x < TAIL_TILES) g_flags[threadIdx.x] = 0;

    if (blockIdx.x < TILEX_BLOCKS) {
        // ---- tile_x: fp16 X -> tiled+swizzled, one 16B chunk per thread ----
        const size_t i = (size_t)blockIdx.x * 256 + threadIdx.x;
        const int m  = (int)(i >> 9);      // K/8 = 512 chunks per row
        const int c8 = (int)(i & 511);
        const int kc = c8 >> 3;
        const int c  = c8 & 7;
        float4 v0 = x[(size_t)m * 1024 + c8 * 2];
        float4 v1 = x[(size_t)m * 1024 + c8 * 2 + 1];
        __half2 h0 = __floats2half2_rn(v0.x, v0.y);
        __half2 h1 = __floats2half2_rn(v0.z, v0.w);
        __half2 h2 = __floats2half2_rn(v1.x, v1.y);
        __half2 h3 = __floats2half2_rn(v1.z, v1.w);
        uint4 p;
        p.x = reinterpret_cast<uint32_t&>(h0);
        p.y = reinterpret_cast<uint32_t&>(h1);
        p.z = reinterpret_cast<uint32_t&>(h2);
        p.w = reinterpret_cast<uint32_t&>(h3);
        const size_t idx16 = ((size_t)kc * MDIM + m) * 8 + (c ^ (m & 7));
        reinterpret_cast<uint4*>(g_Xh)[idx16] = p;
    } else {
        // ---- dequant: q[K,N] codes -> fp16 W^T tiled+swizzled ----
        __shared__ __half tile[32][72];    // [n_local][k_local], 144B row stride
        const int pb = blockIdx.x - TILEX_BLOCKS;
        const int n0 = (pb % DEQ_NB) * 32;
        const int kc = pb / DEQ_NB;
        const int k0 = kc * 64;
        const int tx = threadIdx.x & 31;   // n lane
        const int ty = threadIdx.x >> 5;   // 0..7

        const float s = scale[(size_t)kc * NDIM + n0 + tx];
        const float z = zp[(size_t)kc * NDIM + n0 + tx];
#pragma unroll
        for (int r = 0; r < 8; ++r) {
            const int kl = ty + r * 8;
            const int qq = q[(size_t)(k0 + kl) * NDIM + n0 + tx];
            tile[tx][kl] = __float2half((float)qq * s + z);
        }
        __syncthreads();

        const int t = threadIdx.x;
        const int n_local = t >> 3;
        const int c_store = t & 7;
        const int n = n0 + n_local;
        const int c_src = c_store ^ (n & 7);
        const uint4 v = *reinterpret_cast<const uint4*>(&tile[n_local][c_src * 8]);
        reinterpret_cast<uint4*>(g_Wt)[((size_t)kc * NDIM + n) * 8 + c_store] = v;
    }
}

// ---------------------------------------------------------------------------
// PTX helpers (sm_90-standard, compute_103-safe)
// ---------------------------------------------------------------------------
__device__ __forceinline__ uint32_t smem_u32(const void* p) {
    uint32_t a;
    asm("{ .reg .u64 t; cvta.to.shared.u64 t, %1; cvt.u32.u64 %0, t; }" : "=r"(a) : "l"(p));
    return a;
}

__device__ __forceinline__ void mbar_init(uint32_t a, uint32_t cnt) {
    asm volatile("mbarrier.init.shared.b64 [%0], %1;" :: "r"(a), "r"(cnt) : "memory");
}

__device__ __forceinline__ void mbar_expect(uint32_t a, uint32_t bytes) {
    asm volatile("mbarrier.arrive.expect_tx.shared.b64 _, [%0], %1;"
                 :: "r"(a), "r"(bytes) : "memory");
}

__device__ __forceinline__ void mbar_wait(uint32_t a, uint32_t parity) {
    asm volatile(
        "{\n\t.reg .pred P;\n\t"
        "W%=:\n\t"
        "mbarrier.try_wait.parity.shared.b64 P, [%0], %1;\n\t"
        "@P bra D%=;\n\t"
        "bra W%=;\n\t"
        "D%=:\n\t}"
        :: "r"(a), "r"(parity) : "memory");
}

__device__ __forceinline__ void bulk_g2s(uint32_t dst, const void* src,
                                         uint32_t bytes, uint32_t mb) {
    asm volatile(
        "cp.async.bulk.shared::cluster.global.mbarrier::complete_tx::bytes "
        "[%0], [%1], %2, [%3];"
        :: "r"(dst), "l"(src), "r"(bytes), "r"(mb) : "memory");
}

__device__ __forceinline__ void fence_proxy_async() {
    asm volatile("fence.proxy.async.shared::cta;" ::: "memory");
}

__device__ __forceinline__ void flag_release(unsigned* p) {
    asm volatile("st.global.release.gpu.u32 [%0], %1;" :: "l"(p), "r"(1u) : "memory");
}

__device__ __forceinline__ unsigned flag_acquire(const unsigned* p) {
    unsigned v;
    asm volatile("ld.global.acquire.gpu.u32 %0, [%1];" : "=r"(v) : "l"(p) : "memory");
    return v;
}

// ---------------------------------------------------------------------------
// Main GEMM: out[M,N] = fp16(X)@W + bias, fp32 accumulate
// Stage layout: A 16K @+0 | B 16K @+16384
// bid < FULL_TILES: full-K tile. Else: tail half-K CTA (pair with flag combine).
// ---------------------------------------------------------------------------
__global__ void __launch_bounds__(NTHREADS, 2)
w2a16_gemm_kernel(const float* __restrict__ bias, float* __restrict__ out) {
    extern __shared__ char smem_raw[];
    uint32_t sb0 = smem_u32(smem_raw);
    uint32_t sb = (sb0 + 1023) & ~1023u;
    const uint32_t mbar = sb;                 // 3 x 8B mbarriers
    const uint32_t stage0 = sb + 1024;

    const int tid = threadIdx.x;
    const int wid = tid >> 5;
    const int lid = tid & 31;

    // Tile assignment + K-range
    const int bid = blockIdx.x;
    int tile, kbase, kiters, mode, pairid = 0;
    if (bid < FULL_TILES) {
        tile = bid; kbase = 0; kiters = KITERS; mode = 0;
    } else {
        const int e = bid - FULL_TILES;
        pairid = e >> 1;
        tile = FULL_TILES + pairid;
        const int half = e & 1;
        kbase = half * (KITERS / 2);
        kiters = KITERS / 2;
        mode = 1 + half;                       // 1: store+flag, 2: wait+RMW
    }
    const int m0 = (tile & 31) * TM;
    const int n0 = (tile >> 5) * TN;

    const int warp_m = wid & 1;        // 0..1 -> m offset 64*warp_m
    const int warp_n = wid >> 1;       // 0..1 -> n offset 64*warp_n

    const char* xbase = reinterpret_cast<const char*>(g_Xh);
    const char* wbase = reinterpret_cast<const char*>(g_Wt);

    if (tid == 0) {
#pragma unroll
        for (int s = 0; s < STAGES; ++s) mbar_init(mbar + 8 * s, 1);
    }
    fence_proxy_async();
    __syncthreads();

    // Prologue fills: 2 bulk ops per stage (A 16K, B 16K)
    if (tid == 0) {
#pragma unroll
        for (int s = 0; s < STAGES; ++s) {
            const uint32_t st = stage0 + s * STAGE_BYTES;
            mbar_expect(mbar + 8 * s, STAGE_BYTES);
            bulk_g2s(st,         xbase + ((size_t)(kbase + s) * MDIM + m0) * 128, 16384, mbar + 8 * s);
            bulk_g2s(st + 16384, wbase + ((size_t)(kbase + s) * NDIM + n0) * 128, 16384, mbar + 8 * s);
        }
    }

    float acc[4][8][4];
#pragma unroll
    for (int i = 0; i < 4; ++i)
#pragma unroll
        for (int j = 0; j < 8; ++j)
#pragma unroll
            for (int c = 0; c < 4; ++c) acc[i][j][c] = 0.f;

    // Per-lane ldmatrix addressing components (row * 128B)
    const uint32_t rbA = (uint32_t)(warp_m * 64 + (lid & 15)) * 128;
    const uint32_t colA = (uint32_t)((lid >> 4) * 16);        // +8 halves
    const uint32_t rbB = (uint32_t)(warp_n * 64 + ((lid >> 4) & 1) * 8 + (lid & 7)) * 128;
    const uint32_t colB = (uint32_t)(((lid >> 3) & 1) * 16);  // +8 halves

    int s = 0, ph = 0;                  // rolling stage cursor (3 = non-pow2)
    for (int kk = 0; kk < kiters; ++kk) {
        const uint32_t stage_sm = stage0 + s * STAGE_BYTES;

        mbar_wait(mbar + 8 * s, ph);

#pragma unroll
        for (int ks = 0; ks < 4; ++ks) {
            const uint32_t kb = (uint32_t)ks * 32;   // 16 halves per k-step

            // A fragments: 4 x4-ldmatrix -> 4 m16-tiles
            uint32_t a[4][4];
#pragma unroll
            for (int mt = 0; mt < 4; ++mt) {
                uint32_t raw = rbA + (uint32_t)mt * 2048 + kb + colA;
                uint32_t addr = stage_sm + (raw ^ ((raw >> 3) & 0x70));
                asm volatile(
                    "ldmatrix.sync.aligned.m8n8.x4.shared.b16 {%0,%1,%2,%3}, [%4];"
                    : "=r"(a[mt][0]), "=r"(a[mt][1]), "=r"(a[mt][2]), "=r"(a[mt][3])
                    : "r"(addr));
            }

            // B fragments: 4 x4-ldmatrix -> 8 n8-tiles
            uint32_t b0[4], b1[4], b2[4], b3[4];
            uint32_t* bt[4] = {b0, b1, b2, b3};
#pragma unroll
            for (int t = 0; t < 4; ++t) {
                uint32_t raw = rbB + (uint32_t)t * 2048 + kb + colB;
                uint32_t addr = stage_sm + 16384 + (raw ^ ((raw >> 3) & 0x70));
                asm volatile(
                    "ldmatrix.sync.aligned.m8n8.x4.shared.b16 {%0,%1,%2,%3}, [%4];"
                    : "=r"(bt[t][0]), "=r"(bt[t][1]), "=r"(bt[t][2]), "=r"(bt[t][3])
                    : "r"(addr));
            }

            // 32 MMAs per fragment set (ratio 4 MMA:LDSM)
#pragma unroll
            for (int mt = 0; mt < 4; ++mt) {
#pragma unroll
                for (int t = 0; t < 4; ++t) {
#pragma unroll
                    for (int half = 0; half < 2; ++half) {
                        const int ni = t * 2 + half;
                        float* c = acc[mt][ni];
                        uint32_t bb0 = bt[t][half * 2];
                        uint32_t bb1 = bt[t][half * 2 + 1];
                        asm volatile(
                            "mma.sync.aligned.m16n8k16.row.col.f32.f16.f16.f32 "
                            "{%0,%1,%2,%3}, {%4,%5,%6,%7}, {%8,%9}, {%0,%1,%2,%3};"
                            : "+f"(c[0]), "+f"(c[1]), "+f"(c[2]), "+f"(c[3])
                            : "r"(a[mt][0]), "r"(a[mt][1]), "r"(a[mt][2]), "r"(a[mt][3]),
                              "r"(bb0), "r"(bb1));
                    }
                }
            }
        }

        __syncthreads();   // all LDS reads of stage s consumed before refill
                           // (MMAs before barrier force ldmatrix completion —
                           //  required for cross-proxy safety vs TMA write)

        const int nk = kk + STAGES;
        if (nk < kiters && tid == 0) {
            const uint32_t st = stage_sm;
            mbar_expect(mbar + 8 * s, STAGE_BYTES);
            bulk_g2s(st,         xbase + ((size_t)(kbase + nk) * MDIM + m0) * 128, 16384, mbar + 8 * s);
            bulk_g2s(st + 16384, wbase + ((size_t)(kbase + nk) * NDIM + n0) * 128, 16384, mbar + 8 * s);
        }

        if (++s == STAGES) { s = 0; ph ^= 1; }
    }

    // Epilogue
    const int mrow0 = m0 + warp_m * 64 + (lid >> 2);
    const int ncol0 = n0 + warp_n * 64 + (lid & 3) * 2;
    if (mode < 2) {
        // Full tile or tail-half 0: out = acc + bias
#pragma unroll
        for (int mt = 0; mt < 4; ++mt) {
#pragma unroll
            for (int ni = 0; ni < 8; ++ni) {
                const int n = ncol0 + ni * 8;
                const float bx = bias[n];
                const float by = bias[n + 1];
                const int mA = mrow0 + mt * 16;
                float2 v0 = {acc[mt][ni][0] + bx, acc[mt][ni][1] + by};
                float2 v1 = {acc[mt][ni][2] + bx, acc[mt][ni][3] + by};
                *reinterpret_cast<float2*>(out + (size_t)mA * NDIM + n) = v0;
                *reinterpret_cast<float2*>(out + (size_t)(mA + 8) * NDIM + n) = v1;
            }
        }
        if (mode == 1) {
            __threadfence();
            __syncthreads();
            if (tid == 0) flag_release(&g_flags[pairid]);
        }
    } else {
        // Tail-half 1: wait for half 0's store, then read-modify-write (no bias)
        if (tid == 0) {
            while (flag_acquire(&g_flags[pairid]) == 0) { }
        }
        __syncthreads();
#pragma unroll
        for (int mt = 0; mt < 4; ++mt) {
#pragma unroll
            for (int ni = 0; ni < 8; ++ni) {
                const int n = ncol0 + ni * 8;
                const int mA = mrow0 + mt * 16;
                float2* p0 = reinterpret_cast<float2*>(out + (size_t)mA * NDIM + n);
                float2* p1 = reinterpret_cast<float2*>(out + (size_t)(mA + 8) * NDIM + n);
                float2 o0 = *p0;
                float2 o1 = *p1;
                o0.x += acc[mt][ni][0]; o0.y += acc[mt][ni][1];
                o1.x += acc[mt][ni][2]; o1.y += acc[mt][ni][3];
                *p0 = o0;
                *p1 = o1;
            }
        }
    }
}

// ---------------------------------------------------------------------------
// Launch
// ---------------------------------------------------------------------------
extern "C" void kernel_launch(void* const* d_in, const int* in_sizes, int n_in,
                              void* d_out, int out_size) {
    (void)in_sizes; (void)n_in; (void)out_size;
    const float* input   = (const float*)d_in[0];
    const int*   qweight = (const int*)d_in[1];
    const float* scale   = (const float*)d_in[2];
    const float* zp      = (const float*)d_in[3];
    const float* bias    = (const float*)d_in[4];
    float* out = (float*)d_out;

    cudaFuncSetAttribute(w2a16_gemm_kernel,
                         cudaFuncAttributeMaxDynamicSharedMemorySize, SMEM_TOTAL);

    prepass_kernel<<<PREP_BLOCKS, 256>>>(
        reinterpret_cast<const float4*>(input), qweight, scale, zp);
    w2a16_gemm_kernel<<<GRIDSZ, NTHREADS, SMEM_TOTAL>>>(bias, out);
}